// round 13
// baseline (speedup 1.0000x reference)
#include <cuda_runtime.h>
#include <cuda_fp16.h>
#include <math.h>

#define CC    10
#define CH    5        // capsules per chunk
#define NN    1152
#define DIN   8
#define DOUT  16
#define BB    256

typedef unsigned long long ull;

// fp16 priors scratch for ONE 5-capsule chunk: [c_local][b][n][o] = 47.2 MB.
// Reused in place by the second chunk -> dead dirty lines rarely hit DRAM.
__device__ __half g_pri[(size_t)CH * BB * NN * DOUT];

// ---- packed f32x2 helpers (Blackwell FFMA2 — PTX-only) ----
__device__ __forceinline__ ull pack2(float lo, float hi) {
    ull r; asm("mov.b64 %0, {%1, %2};" : "=l"(r) : "f"(lo), "f"(hi)); return r;
}
__device__ __forceinline__ float2 unpack2(ull v) {
    float2 f; asm("mov.b64 {%0, %1}, %2;" : "=f"(f.x), "=f"(f.y) : "l"(v)); return f;
}
__device__ __forceinline__ ull fma2(ull a, ull b, ull c) {
    ull d; asm("fma.rn.f32x2 %0, %1, %2, %3;" : "=l"(d) : "l"(a), "l"(b), "l"(c)); return d;
}
__device__ __forceinline__ ull add2(ull a, ull b) {
    ull d; asm("add.rn.f32x2 %0, %1, %2;" : "=l"(d) : "l"(a), "l"(b)); return d;
}
__device__ __forceinline__ ull h2_to_f32x2(unsigned int h2) {
    ull d;
    asm("{\n\t"
        ".reg .f16 h0, h1;\n\t"
        ".reg .f32 f0, f1;\n\t"
        "mov.b32 {h0, h1}, %1;\n\t"
        "cvt.f32.f16 f0, h0;\n\t"
        "cvt.f32.f16 f1, h1;\n\t"
        "mov.b64 %0, {f0, f1};\n\t"
        "}" : "=l"(d) : "r"(h2));
    return d;
}
__device__ __forceinline__ unsigned int f32x2_to_h2(ull v) {
    unsigned int r;
    asm("{\n\t"
        ".reg .f32 lo, hi;\n\t"
        "mov.b64 {lo, hi}, %1;\n\t"
        "cvt.rn.f16x2.f32 %0, hi, lo;\n\t"
        "}" : "=r"(r) : "l"(v));
    return r;
}

// ================= Kernel 1: priors GEMM (fp32 W) -> g_pri fp16 (chunk-local) =================
// grid (CH, 9, 8); 256 threads. Thread owns (node n, o-half oh), loops 32 batch elems.
#define ZB 8
#define BPB (BB / ZB)   // 32 batch elems per block

__global__ __launch_bounds__(256)
void priors_kernel(const float* __restrict__ x, const float* __restrict__ W, int c0) {
    const int tid = threadIdx.x;
    const int oh  = tid & 1;                   // o-half: owns o = oh*8 .. oh*8+7
    const int nn  = tid >> 1;                  // 0..127
    const int cl  = blockIdx.x;                // chunk-local capsule
    const int cg  = c0 + cl;                   // global capsule (for W)
    const int n   = blockIdx.y * 128 + nn;
    const int b0  = blockIdx.z * BPB;

    // Load this (n, oh) W slice ONCE: 8 i x 8 o = 64 floats -> 32 f32x2 regs.
    ull w2[32];
    {
        const float4* wr = reinterpret_cast<const float4*>(
            W + (((size_t)cg * NN + n) * DIN) * DOUT + oh * 8);
#pragma unroll
        for (int i = 0; i < 8; ++i) {
            float4 q0 = wr[i * 4 + 0];
            float4 q1 = wr[i * 4 + 1];
            w2[i * 4 + 0] = pack2(q0.x, q0.y);
            w2[i * 4 + 1] = pack2(q0.z, q0.w);
            w2[i * 4 + 2] = pack2(q1.x, q1.y);
            w2[i * 4 + 3] = pack2(q1.z, q1.w);
        }
    }

    uint4* op = reinterpret_cast<uint4*>(g_pri);

#pragma unroll 2
    for (int bb = 0; bb < BPB; ++bb) {
        const int b = b0 + bb;
        const float4* xr = reinterpret_cast<const float4*>(x + ((size_t)b * NN + n) * DIN);
        float4 v0 = xr[0], v1 = xr[1];
        float xa[8];
        xa[0]=v0.x; xa[1]=v0.y; xa[2]=v0.z; xa[3]=v0.w;
        xa[4]=v1.x; xa[5]=v1.y; xa[6]=v1.z; xa[7]=v1.w;

        ull acc[4] = {0ull, 0ull, 0ull, 0ull};
#pragma unroll
        for (int i = 0; i < 8; ++i) {
            ull xs = pack2(xa[i], xa[i]);
#pragma unroll
            for (int p = 0; p < 4; ++p)
                acc[p] = fma2(xs, w2[i * 4 + p], acc[p]);
        }
        uint4 o;
        o.x = f32x2_to_h2(acc[0]);
        o.y = f32x2_to_h2(acc[1]);
        o.z = f32x2_to_h2(acc[2]);
        o.w = f32x2_to_h2(acc[3]);
        op[((size_t)(cl * BB + b) * NN + n) * 2 + oh] = o;
    }
}

// ================= Kernel 2: routing, fp32 priors tile in SMEM =================
// grid (CH, BB); 512 threads (16 warps), 2 CTAs/SM.
// Tile converted fp16->fp32 ONCE at load; scans read packed f32x2 directly.
#define T3    512
#define NW3   16
#define KPT3  9    // nodes per thread: NN / (T3/4)

// dynamic smem layout (floats): spri32[NN*16] | red[16*NW3] | sew[NW3] | outv[16]
#define SMR_PRI  0
#define SMR_RED  (NN * DOUT)
#define SMR_SEW  (SMR_RED + 16 * NW3)
#define SMR_OUT  (SMR_SEW + NW3)
#define SMR_TOT  (SMR_OUT + 16)

__global__ __launch_bounds__(T3, 2)
void routing_kernel(float* __restrict__ out, int c0) {
    extern __shared__ __align__(16) float smr[];
    float* spri = smr + SMR_PRI;
    float* red  = smr + SMR_RED;
    float* sew  = smr + SMR_SEW;
    float* outv = smr + SMR_OUT;

    const int tid  = threadIdx.x;
    const int lane = tid & 31;
    const int wid  = tid >> 5;
    const int oq   = tid & 3;     // owns o = oq*4 .. oq*4+3
    const int g    = tid >> 2;    // node group 0..127
    const int cl   = blockIdx.x;  // chunk-local capsule
    const int cg   = c0 + cl;     // global capsule (for out)
    const int b    = blockIdx.y;

    // ---- load priors tile + convert fp16->fp32 ONCE (4608 uint2, coalesced) ----
    {
        const uint2* src = reinterpret_cast<const uint2*>(g_pri)
                         + (size_t)(cl * BB + b) * NN * 4;
#pragma unroll
        for (int k = 0; k < KPT3; ++k) {
            uint2 hv = src[tid + T3 * k];
            float2 a = unpack2(h2_to_f32x2(hv.x));
            float2 c = unpack2(h2_to_f32x2(hv.y));
            *reinterpret_cast<float4*>(&spri[(size_t)(tid + T3 * k) * 4]) =
                make_float4(a.x, a.y, c.x, c.y);
        }
    }
    __syncthreads();

    // ---- iter 0: uniform weights -> s = mean over n, squash ----
    {
        ull s2[2] = {0ull, 0ull};
#pragma unroll
        for (int k = 0; k < KPT3; ++k) {
            const ull* p = reinterpret_cast<const ull*>(
                &spri[(size_t)(((g + 128 * k) << 2) + oq) * 4]);
            s2[0] = add2(s2[0], p[0]);
            s2[1] = add2(s2[1], p[1]);
        }
        float s[4];
        { float2 a = unpack2(s2[0]), c = unpack2(s2[1]);
          s[0]=a.x; s[1]=a.y; s[2]=c.x; s[3]=c.y; }
        // reduce across the 8 node-groups within each warp (keep oq bits distinct)
        for (int m = 4; m < 32; m <<= 1)
#pragma unroll
            for (int j = 0; j < 4; ++j)
                s[j] += __shfl_xor_sync(0xffffffffu, s[j], m);
        if (lane < 4)
#pragma unroll
            for (int j = 0; j < 4; ++j)
                red[(lane * 4 + j) * NW3 + wid] = s[j];
    }
    __syncthreads();
    if (tid < 16) {   // lanes 0..15 of warp 0 -> mask 0xffff
        const int o = tid;
        float s = 0.0f;
#pragma unroll
        for (int w = 0; w < NW3; ++w) s += red[o * NW3 + w];
        s *= (1.0f / (float)NN);
        float q = s * s;
        for (int m = 1; m < 16; m <<= 1) q += __shfl_xor_sync(0xffffu, q, m);
        float scale = q / ((1.0f + q) * sqrtf(q));
        outv[o] = scale * s;
    }

    // ---- iterations 1..2: fused agreement + exp + weighted sum ----
    float lg[KPT3];
#pragma unroll
    for (int k = 0; k < KPT3; ++k) lg[k] = 0.0f;

    for (int it = 1; it <= 2; ++it) {
        __syncthreads();
        const ull* ovp = reinterpret_cast<const ull*>(outv + oq * 4);
        const ull ov0 = ovp[0];
        const ull ov1 = ovp[1];

        ull sp0 = 0ull, sp1 = 0ull;
        float se = 0.0f;
#pragma unroll
        for (int k = 0; k < KPT3; ++k) {
            const ull* pp = reinterpret_cast<const ull*>(
                &spri[(size_t)(((g + 128 * k) << 2) + oq) * 4]);
            ull p0 = pp[0], p1 = pp[1];
            // agreement quad-dot (no max pass — exp safe since ||out||<1 bounds logits)
            ull d2 = fma2(p0, ov0, fma2(p1, ov1, 0ull));
            float2 dd = unpack2(d2);
            float d = dd.x + dd.y;
            d += __shfl_xor_sync(0xffffffffu, d, 1);   // combine 4 o-quads
            d += __shfl_xor_sync(0xffffffffu, d, 2);
            lg[k] += d;
            // unnormalized softmax weight + weighted sum
            float e = __expf(lg[k]);
            se += e;
            ull e2 = pack2(e, e);
            sp0 = fma2(e2, p0, sp0);
            sp1 = fma2(e2, p1, sp1);
        }
        float sp[4];
        { float2 a = unpack2(sp0), c = unpack2(sp1);
          sp[0]=a.x; sp[1]=a.y; sp[2]=c.x; sp[3]=c.y; }
        // se: full-warp reduce (4x oq redundancy -> exactly 4*true)
        for (int m = 1; m < 32; m <<= 1)
            se += __shfl_xor_sync(0xffffffffu, se, m);
        // sp: reduce across node-groups only (keep oq distinct)
        for (int m = 4; m < 32; m <<= 1)
#pragma unroll
            for (int j = 0; j < 4; ++j)
                sp[j] += __shfl_xor_sync(0xffffffffu, sp[j], m);
        if (lane == 0) sew[wid] = se;
        if (lane < 4)
#pragma unroll
            for (int j = 0; j < 4; ++j)
                red[(lane * 4 + j) * NW3 + wid] = sp[j];
        __syncthreads();

        if (tid < 16) {   // lanes 0..15 of warp 0 -> mask 0xffff
            const int o = tid;
            float sps = 0.0f, ses = 0.0f;
#pragma unroll
            for (int w = 0; w < NW3; ++w) {
                sps += red[o * NW3 + w];
                ses += sew[w];
            }
            float s = sps * (4.0f / ses);   // /4 undoes oq redundancy exactly
            float q = s * s;
            for (int m = 1; m < 16; m <<= 1) q += __shfl_xor_sync(0xffffu, q, m);
            float scale = q / ((1.0f + q) * sqrtf(q));
            float o_ = scale * s;
            outv[o] = o_;
            if (it == 2)
                out[((size_t)cg * BB + b) * DOUT + o] = o_;
        }
    }
}

extern "C" void kernel_launch(void* const* d_in, const int* in_sizes, int n_in,
                              void* d_out, int out_size) {
    const float* x = (const float*)d_in[0];   // [256,1152,8]
    const float* W = (const float*)d_in[1];   // [10,1152,8,16]
    float* out = (float*)d_out;               // [10,256,1,16]

    const int smem_bytes = SMR_TOT * (int)sizeof(float);   // ~74.9 KB
    cudaFuncSetAttribute(routing_kernel,
                         cudaFuncAttributeMaxDynamicSharedMemorySize, smem_bytes);

    dim3 gp(CH, NN / 128, ZB);                // (5, 9, 8)
    dim3 gr(CH, BB);                          // (5, 256)

    // Chunked pipeline (R11 structure): each 47MB priors chunk is written,
    // consumed by the next kernel, then overwritten in place by chunk 2.
    priors_kernel<<<gp, 256>>>(x, W, 0);
    routing_kernel<<<gr, T3, smem_bytes>>>(out, 0);
    priors_kernel<<<gp, 256>>>(x, W, CH);
    routing_kernel<<<gr, T3, smem_bytes>>>(out, CH);
}